// round 8
// baseline (speedup 1.0000x reference)
#include <cuda_runtime.h>
#include <cuda_bf16.h>

#define N_NODES  50000
#define N_EDGES  1600000
#define BATCH    4
#define T_STEPS  50
#define DT_CONST 0.02f

#define NCTA     444           // 3 CTAs/SM on 148 SMs (proven resident in R6)
#define NTHREADS 512
#define CHUNK    113           // ceil(50000/444)
#define TN       (T_STEPS * N_NODES)

// ---------------- device scratch (static, no allocation) ----------------
__device__ int      g_deg[N_NODES];
__device__ int      g_colptr[N_NODES + 1];  // CSC: by SOURCE
__device__ int      g_cursor[N_NODES];
__device__ int2     g_tw[N_EDGES];          // {w as bits, tgt}, sorted by src
__device__ int      g_srcS[N_EDGES];        // src per sorted slot
__device__ float2   g_ab[N_NODES];          // {alpha, bias}
__device__ float4   g_V[N_NODES];           // membrane potential, [n] x batch
__device__ float4   g_Rt[N_NODES];          // rates relu(v), single buffer
__device__ float4   g_ACC[2][N_NODES];      // double-buffered synaptic accumulators
__device__ int      g_blockSum[NCTA];
__device__ unsigned g_bar;

// ---------------- grid barrier (monotone counter, reset by init kernel) ----------------
__device__ __forceinline__ void grid_bar(unsigned k) {
    __syncthreads();
    if (threadIdx.x == 0) {
        __threadfence();
        atomicAdd(&g_bar, 1u);
        const unsigned target = k * (unsigned)NCTA;
        while (*(volatile unsigned*)&g_bar < target) { }
    }
    __syncthreads();
}

// ---------------- block-wide inclusive scan (Kogge-Stone in smem) ----------------
__device__ int block_scan_incl(int v) {
    __shared__ int ss[NTHREADS];
    const int tid = threadIdx.x;
    ss[tid] = v;
    __syncthreads();
#pragma unroll
    for (int off = 1; off < NTHREADS; off <<= 1) {
        int t = 0;
        if (tid >= off) t = ss[tid - off];
        __syncthreads();
        if (tid >= off) ss[tid] += t;
        __syncthreads();
    }
    return ss[tid];
}

// ---------------- init kernel: reset per-launch mutable state ----------------
__global__ void init_kernel() {
    int i = blockIdx.x * blockDim.x + threadIdx.x;
    if (i == 0) g_bar = 0u;
    for (int n = i; n < N_NODES; n += gridDim.x * blockDim.x) g_deg[n] = 0;
}

// ---------------- main persistent kernel ----------------
__global__ void __launch_bounds__(NTHREADS, 3) net_kernel(
    const float* __restrict__ x,       // [B, T, N]
    const float* __restrict__ bias,    // [N]
    const float* __restrict__ tconst,  // [N]
    const float* __restrict__ sign,    // [E]
    const float* __restrict__ cnt,     // [E]
    const float* __restrict__ strg,    // [E]
    const int*   __restrict__ src,     // [E]
    const int*   __restrict__ tgt,     // [E]
    float*       __restrict__ out)     // [B, T, N]
{
    const int tid  = threadIdx.x;
    const int bid  = blockIdx.x;
    const int gtid = bid * NTHREADS + tid;
    const int nthr = NCTA * NTHREADS;
    unsigned barK = 0;

    // ---- Pass A: degree histogram over SOURCES (CSC) ----
    for (int e = gtid; e < N_EDGES; e += nthr)
        atomicAdd(&g_deg[src[e]], 1);
    grid_bar(++barK);

    // ---- Pass B1: per-CTA chunk sums ----
    {
        const int n = bid * CHUNK + tid;
        int v = (tid < CHUNK && n < N_NODES) ? g_deg[n] : 0;
        int incl = block_scan_incl(v);
        if (tid == NTHREADS - 1) g_blockSum[bid] = incl;
    }
    grid_bar(++barK);

    // ---- Pass B2: CTA0 exclusive-scans the block sums ----
    if (bid == 0) {
        int v = (tid < NCTA) ? g_blockSum[tid] : 0;
        int incl = block_scan_incl(v);
        if (tid < NCTA) g_blockSum[tid] = incl - v;
    }
    grid_bar(++barK);

    // ---- Pass B3: per-chunk exclusive scan -> col_ptr & cursor ----
    {
        const int n = bid * CHUNK + tid;
        int v = (tid < CHUNK && n < N_NODES) ? g_deg[n] : 0;
        int incl = block_scan_incl(v);
        if (tid < CHUNK && n < N_NODES) {
            int cp = g_blockSum[bid] + incl - v;
            g_colptr[n] = cp;
            g_cursor[n] = cp;
        }
        if (gtid == 0) g_colptr[N_NODES] = N_EDGES;
    }
    grid_bar(++barK);

    // ---- Pass C: scatter edges into src-sorted slots, fused weight compute ----
    for (int e = gtid; e < N_EDGES; e += nthr) {
        float w = sign[e] * fmaxf(cnt[e], 0.0f) * fmaxf(strg[e], 0.0f);
        int  s = src[e];
        int  p = atomicAdd(&g_cursor[s], 1);
        g_tw[p]   = make_int2(__float_as_int(w), tgt[e]);
        g_srcS[p] = s;
    }

    // ---- Pass D: node state init; zero both accumulators ----
    for (int n = gtid; n < N_NODES; n += nthr) {
        float b   = bias[n];
        float tau = fmaxf(tconst[n], DT_CONST);
        g_ab[n] = make_float2(DT_CONST / tau, b);
        float r = fmaxf(b, 0.0f);
        g_V[n]      = make_float4(b, b, b, b);
        g_Rt[n]     = make_float4(r, r, r, r);
        g_ACC[0][n] = make_float4(0.f, 0.f, 0.f, 0.f);
        g_ACC[1][n] = make_float4(0.f, 0.f, 0.f, 0.f);
    }
    grid_bar(++barK);

    // ---- Hot loop: 50 steps of [scatter | bar | Euler(+rezero) | bar] ----
    const int  n_node   = bid * CHUNK + tid;                 // Euler node for this thread
    const bool has_node = (tid < CHUNK) && (n_node < N_NODES);

    for (int t = 0; t < T_STEPS; t++) {
        float4* __restrict__ acc = g_ACC[t & 1];

        // Prefetch this step's stimulus early; latency hides behind the scatter phase.
        float x0 = 0.f, x1 = 0.f, x2 = 0.f, x3 = 0.f;
        if (has_node) {
            const float* xt = x + t * N_NODES;
            x0 = __ldcg(xt + 0 * TN + n_node);
            x1 = __ldcg(xt + 1 * TN + n_node);
            x2 = __ldcg(xt + 2 * TN + n_node);
            x3 = __ldcg(xt + 3 * TN + n_node);
        }

        // ---- Scatter phase: src-sorted edges, broadcast gather + v4 reduction ----
#pragma unroll 4
        for (int e = gtid; e < N_EDGES; e += nthr) {
            int  s  = __ldg(&g_srcS[e]);          // coalesced, warp-near-uniform
            int2 wt = __ldg(&g_tw[e]);            // coalesced
            float4 r = __ldcg(&g_Rt[s]);          // warp-uniform -> ~1 wavefront
            float  w = __int_as_float(wt.x);
            float4* p = &acc[wt.y];
            asm volatile("red.global.add.v4.f32 [%0], {%1, %2, %3, %4};"
                         :: "l"(p), "f"(w * r.x), "f"(w * r.y),
                            "f"(w * r.z), "f"(w * r.w)
                         : "memory");             // fire-and-forget
        }
        grid_bar(++barK);

        // ---- Euler phase: one thread per node, then re-zero accum for t+2 ----
        if (has_node) {
            float4 a  = __ldcg(&acc[n_node]);     // atomics landed in L2
            float2 ab = g_ab[n_node];             // L1-hit (same thread each step)
            float4 v  = g_V[n_node];              // L1-hit
            v.x = fmaf(ab.x, (ab.y - v.x) + (a.x + x0), v.x);
            v.y = fmaf(ab.x, (ab.y - v.y) + (a.y + x1), v.y);
            v.z = fmaf(ab.x, (ab.y - v.z) + (a.z + x2), v.z);
            v.w = fmaf(ab.x, (ab.y - v.w) + (a.w + x3), v.w);
            g_V[n_node] = v;

            float4 rr = make_float4(fmaxf(v.x, 0.f), fmaxf(v.y, 0.f),
                                    fmaxf(v.z, 0.f), fmaxf(v.w, 0.f));
            g_Rt[n_node] = rr;                    // write-through -> L2 (proven R1-R7)

            float* ot = out + t * N_NODES;
            ot[0 * TN + n_node] = rr.x;
            ot[1 * TN + n_node] = rr.y;
            ot[2 * TN + n_node] = rr.z;
            ot[3 * TN + n_node] = rr.w;

            acc[n_node] = make_float4(0.f, 0.f, 0.f, 0.f);   // ready for step t+2
        }
        if (t != T_STEPS - 1) grid_bar(++barK);
    }
}

extern "C" void kernel_launch(void* const* d_in, const int* in_sizes, int n_in,
                              void* d_out, int out_size) {
    const float* x      = (const float*)d_in[0];
    const float* bias   = (const float*)d_in[1];
    const float* tconst = (const float*)d_in[2];
    const float* sign   = (const float*)d_in[3];
    const float* cnt    = (const float*)d_in[4];
    const float* strg   = (const float*)d_in[5];
    const int*   src    = (const int*)d_in[6];
    const int*   tgt    = (const int*)d_in[7];
    float*       out    = (float*)d_out;

    init_kernel<<<128, 512>>>();
    net_kernel<<<NCTA, NTHREADS>>>(x, bias, tconst, sign, cnt, strg, src, tgt, out);
}

// round 9
// speedup vs baseline: 1.1027x; 1.1027x over previous
#include <cuda_runtime.h>
#include <cuda_fp16.h>

#define N_NODES  50000
#define N_EDGES  1600000
#define BATCH    4
#define T_STEPS  50
#define DT_CONST 0.02f

#define NCTA     444           // 3 CTAs/SM on 148 SMs (proven resident R6)
#define NTHREADS 512
#define CHUNK    113           // ceil(50000/444)
#define TN       (T_STEPS * N_NODES)
#define QPC      (NTHREADS / 4)              // 128 quads per CTA
#define NQUADS   (NCTA * QPC)                // 56832 quads
#define ECAP     3968                        // sorted-slice capacity (s_c = 62KB)
#define NBKT     391                         // src buckets: (50000+127)>>7

// ---------------- device scratch (static, no allocation) ----------------
__device__ int            g_deg[N_NODES];
__device__ int            g_rowptr[N_NODES + 1];
__device__ int            g_cursor[N_NODES];
__device__ int            g_rowLo[NQUADS + 1];
__device__ int2           g_ws[N_EDGES];      // {w bits, src} in CSR(row) order
__device__ int2           g_sorted[N_EDGES];  // {w bits, src} bucket-sorted per CTA slice
__device__ unsigned short g_slots[N_EDGES];   // CSR edge -> sorted slot (CTA-local)
__device__ float2         g_ab[N_NODES];      // {alpha, bias}
__device__ float          g_Vf[N_NODES * 4];  // membrane potential [n][b]
__device__ uint2          g_Rh[2][N_NODES];   // fp16x4 rates, double-buffered
__device__ int            g_blockSum[NCTA];
__device__ unsigned       g_bar;

// ---------------- grid barrier ----------------
__device__ __forceinline__ void grid_bar(unsigned k) {
    __syncthreads();
    if (threadIdx.x == 0) {
        __threadfence();
        atomicAdd(&g_bar, 1u);
        const unsigned target = k * (unsigned)NCTA;
        while (*(volatile unsigned*)&g_bar < target) { }
    }
    __syncthreads();
}

// ---------------- block-wide inclusive scan ----------------
__device__ int block_scan_incl(int v) {
    __shared__ int ss[NTHREADS];
    const int tid = threadIdx.x;
    ss[tid] = v;
    __syncthreads();
#pragma unroll
    for (int off = 1; off < NTHREADS; off <<= 1) {
        int t = 0;
        if (tid >= off) t = ss[tid - off];
        __syncthreads();
        if (tid >= off) ss[tid] += t;
        __syncthreads();
    }
    return ss[tid];
}

__device__ __forceinline__ int quad_of_offset(int off) {
    return (int)(((long long)off * NQUADS) / N_EDGES);
}

__global__ void init_kernel() {
    int i = blockIdx.x * blockDim.x + threadIdx.x;
    if (i == 0) g_bar = 0u;
    for (int n = i; n < N_NODES; n += gridDim.x * blockDim.x) g_deg[n] = 0;
}

// ---------------- fallback hot loop (divergent gather, R5-proven shape) ----------------
__device__ __noinline__ void run_steps_fallback(
    int rowA, int rowB, int q, unsigned qmask,
    const float* __restrict__ x, float* __restrict__ out,
    unsigned& barK)
{
    for (int t = 0; t < T_STEPS; t++) {
        const uint2* __restrict__ Rc  = g_Rh[t & 1];
        uint2*       __restrict__ Rn  = g_Rh[(t + 1) & 1];
        const float* __restrict__ xt  = x + t * N_NODES;
        float*       __restrict__ ot  = out + t * N_NODES;

        for (int r = rowA; r < rowB; ++r) {
            const int beg = g_rowptr[r];
            const int end = g_rowptr[r + 1];
            const float xv = __ldcg(xt + q * TN + r);
            float a0 = 0.f, a1 = 0.f, a2 = 0.f, a3 = 0.f;
            for (int e = beg + q; e < end; e += 4) {
                int2 ws = __ldg(&g_ws[e]);
                uint2 rh = __ldcg(&Rc[ws.y]);
                float w = __int_as_float(ws.x);
                float2 f01 = __half22float2(*reinterpret_cast<__half2*>(&rh.x));
                float2 f23 = __half22float2(*reinterpret_cast<__half2*>(&rh.y));
                a0 = fmaf(w, f01.x, a0); a1 = fmaf(w, f01.y, a1);
                a2 = fmaf(w, f23.x, a2); a3 = fmaf(w, f23.y, a3);
            }
#pragma unroll
            for (int off = 1; off < 4; off <<= 1) {
                a0 += __shfl_xor_sync(qmask, a0, off);
                a1 += __shfl_xor_sync(qmask, a1, off);
                a2 += __shfl_xor_sync(qmask, a2, off);
                a3 += __shfl_xor_sync(qmask, a3, off);
            }
            float acc = (q == 0) ? a0 : (q == 1) ? a1 : (q == 2) ? a2 : a3;
            float2 ab = g_ab[r];
            float  v  = g_Vf[4 * r + q];
            v = fmaf(ab.x, (ab.y - v) + (acc + xv), v);
            g_Vf[4 * r + q] = v;
            float rr = fmaxf(v, 0.0f);
            reinterpret_cast<__half*>(&Rn[r])[q] = __float2half_rn(rr);
            ot[q * TN + r] = rr;
        }
        if (t != T_STEPS - 1) grid_bar(++barK);
    }
}

// ---------------- main persistent kernel ----------------
__global__ void __launch_bounds__(NTHREADS, 3) net_kernel(
    const float* __restrict__ x,       // [B, T, N]
    const float* __restrict__ bias,    // [N]
    const float* __restrict__ tconst,  // [N]
    const float* __restrict__ sign,    // [E]
    const float* __restrict__ cnt,     // [E]
    const float* __restrict__ strg,    // [E]
    const int*   __restrict__ src,     // [E]
    const int*   __restrict__ tgt,     // [E]
    float*       __restrict__ out)     // [B, T, N]
{
    extern __shared__ char dynsmem[];
    float4* s_c    = reinterpret_cast<float4*>(dynsmem);       // 62KB partials
    int*    s_hist = reinterpret_cast<int*>(dynsmem);          // setup-only alias
    int*    s_boff = reinterpret_cast<int*>(dynsmem) + NBKT;

    const int tid  = threadIdx.x;
    const int bid  = blockIdx.x;
    const int gtid = bid * NTHREADS + tid;
    const int nthr = NCTA * NTHREADS;
    unsigned barK = 0;

    // ---- Pass A: degree histogram over targets ----
    for (int e = gtid; e < N_EDGES; e += nthr)
        atomicAdd(&g_deg[tgt[e]], 1);
    grid_bar(++barK);

    // ---- Pass B1: per-CTA chunk sums ----
    {
        const int n = bid * CHUNK + tid;
        int v = (tid < CHUNK && n < N_NODES) ? g_deg[n] : 0;
        int incl = block_scan_incl(v);
        if (tid == NTHREADS - 1) g_blockSum[bid] = incl;
    }
    grid_bar(++barK);

    // ---- Pass B2: CTA0 exclusive-scans block sums ----
    if (bid == 0) {
        int v = (tid < NCTA) ? g_blockSum[tid] : 0;
        int incl = block_scan_incl(v);
        if (tid < NCTA) g_blockSum[tid] = incl - v;
    }
    grid_bar(++barK);

    // ---- Pass B3: row_ptr & cursor ----
    {
        const int n = bid * CHUNK + tid;
        int v = (tid < CHUNK && n < N_NODES) ? g_deg[n] : 0;
        int incl = block_scan_incl(v);
        if (tid < CHUNK && n < N_NODES) {
            int rp = g_blockSum[bid] + incl - v;
            g_rowptr[n] = rp;
            g_cursor[n] = rp;
        }
        if (gtid == 0) g_rowptr[N_NODES] = N_EDGES;
    }
    grid_bar(++barK);

    // ---- Pass C: scatter edges into CSR slots ----
    for (int e = gtid; e < N_EDGES; e += nthr) {
        float w = sign[e] * fmaxf(cnt[e], 0.0f) * fmaxf(strg[e], 0.0f);
        int  t = tgt[e];
        int  p = atomicAdd(&g_cursor[t], 1);
        g_ws[p] = make_int2(__float_as_int(w), src[e]);
    }

    // ---- Edge-balanced quad->row-range partition ----
    for (int r = gtid; r <= N_NODES; r += nthr) {
        int a, b;
        if (r == N_NODES) {
            a = min(quad_of_offset(g_rowptr[N_NODES - 1]), NQUADS - 1) + 1;
            b = NQUADS;
        } else {
            b = min(quad_of_offset(g_rowptr[r]), NQUADS - 1);
            a = (r == 0) ? 0 : min(quad_of_offset(g_rowptr[r - 1]), NQUADS - 1) + 1;
        }
        for (int qq = a; qq <= b; qq++) g_rowLo[qq] = r;
    }

    // ---- Pass D: node state init (fp16 rates) ----
    for (int n = gtid; n < N_NODES; n += nthr) {
        float b   = bias[n];
        float tau = fmaxf(tconst[n], DT_CONST);
        g_ab[n] = make_float2(DT_CONST / tau, b);
        float r = fmaxf(b, 0.0f);
        __half2 h = __floats2half2_rn(r, r);
        uint2 packed;
        packed.x = *reinterpret_cast<unsigned*>(&h);
        packed.y = packed.x;
        g_Rh[0][n] = packed;
        g_Vf[4 * n + 0] = b; g_Vf[4 * n + 1] = b;
        g_Vf[4 * n + 2] = b; g_Vf[4 * n + 3] = b;
    }
    grid_bar(++barK);   // edges + partition + state visible

    // ---- CTA-local bucket sort of its edge slice by src>>7 ----
    const int rowA_cta = g_rowLo[bid * QPC];
    const int rowB_cta = g_rowLo[(bid + 1) * QPC];
    const int ebase    = g_rowptr[rowA_cta];
    const int ecnt     = g_rowptr[rowB_cta] - ebase;
    const bool fits    = (ecnt <= ECAP);

    if (fits) {
        for (int i = tid; i < NBKT; i += NTHREADS) s_hist[i] = 0;
        __syncthreads();
        for (int i = tid; i < ecnt; i += NTHREADS)
            atomicAdd(&s_hist[g_ws[ebase + i].y >> 7], 1);
        __syncthreads();
        {
            int v = (tid < NBKT) ? s_hist[tid] : 0;
            int incl = block_scan_incl(v);
            if (tid < NBKT) s_boff[tid] = incl - v;   // exclusive
        }
        __syncthreads();
        for (int i = tid; i < ecnt; i += NTHREADS) {
            int2 ws = g_ws[ebase + i];
            int pos = atomicAdd(&s_boff[ws.y >> 7], 1);
            g_sorted[ebase + pos] = ws;
            g_slots[ebase + i]    = (unsigned short)pos;
        }
    }
    __syncthreads();

    const int q    = tid & 3;
    const int qid  = gtid >> 2;
    const int rowA = g_rowLo[qid];
    const int rowB = g_rowLo[qid + 1];

    if (!fits) {
        const unsigned qmask = 0xFu << (tid & 28);
        run_steps_fallback(rowA, rowB, q, qmask, x, out, barK);
        return;
    }

    // ---- Hot loop: [bucketed gather -> s_c] | sync | [row reduce + Euler] ----
    const int2* __restrict__ meta = g_sorted + ebase;

    for (int t = 0; t < T_STEPS; t++) {
        const uint2* __restrict__ Rc  = g_Rh[t & 1];
        uint2*       __restrict__ Rn  = g_Rh[(t + 1) & 1];
        const float* __restrict__ xt  = x + t * N_NODES;
        float*       __restrict__ ot  = out + t * N_NODES;

        // Phase 1: consecutive sorted slots per warp -> intra-LDG line sharing
#pragma unroll 2
        for (int i = tid; i < ecnt; i += NTHREADS) {
            int2 m = __ldg(&meta[i]);                  // coalesced, L1-resident
            uint2 rh = __ldcg(&Rc[m.y]);               // 8B, bucketed divergent
            float w = __int_as_float(m.x);
            float2 f01 = __half22float2(*reinterpret_cast<__half2*>(&rh.x));
            float2 f23 = __half22float2(*reinterpret_cast<__half2*>(&rh.y));
            s_c[i] = make_float4(w * f01.x, w * f01.y, w * f23.x, w * f23.y);
        }
        __syncthreads();

        // Phase 2: quad-per-row reduction over s_c via slot permutation (LDS)
        const ulonglong2* __restrict__ sc2 = reinterpret_cast<const ulonglong2*>(s_c);
        for (int r = rowA; r < rowB; ++r) {
            const int beg = g_rowptr[r];               // L1-hit
            const int end = g_rowptr[r + 1];
            const float xv = __ldcg(xt + q * TN + r);

            unsigned long long a01 = 0ull, a23 = 0ull;
#pragma unroll 2
            for (int e = beg + q; e < end; e += 4) {
                unsigned short slot = __ldg(&g_slots[e]);   // coalesced, L1-resident
                ulonglong2 cc = sc2[slot];                  // LDS.128 (crossbar)
                asm("add.rn.f32x2 %0, %1, %2;" : "=l"(a01) : "l"(a01), "l"(cc.x));
                asm("add.rn.f32x2 %0, %1, %2;" : "=l"(a23) : "l"(a23), "l"(cc.y));
            }
            const unsigned qmask = 0xFu << (tid & 28);
#pragma unroll
            for (int off = 1; off < 4; off <<= 1) {
                unsigned long long b01 = __shfl_xor_sync(qmask, a01, off);
                unsigned long long b23 = __shfl_xor_sync(qmask, a23, off);
                asm("add.rn.f32x2 %0, %1, %2;" : "=l"(a01) : "l"(a01), "l"(b01));
                asm("add.rn.f32x2 %0, %1, %2;" : "=l"(a23) : "l"(a23), "l"(b23));
            }
            unsigned long long sel = (q < 2) ? a01 : a23;
            float lo, hi;
            asm("mov.b64 {%0, %1}, %2;" : "=f"(lo), "=f"(hi) : "l"(sel));
            float acc = (q & 1) ? hi : lo;

            float2 ab = g_ab[r];
            float  v  = g_Vf[4 * r + q];
            v = fmaf(ab.x, (ab.y - v) + (acc + xv), v);
            g_Vf[4 * r + q] = v;
            float rr = fmaxf(v, 0.0f);
            reinterpret_cast<__half*>(&Rn[r])[q] = __float2half_rn(rr);
            ot[q * TN + r] = rr;
        }
        if (t != T_STEPS - 1) grid_bar(++barK);
    }
}

extern "C" void kernel_launch(void* const* d_in, const int* in_sizes, int n_in,
                              void* d_out, int out_size) {
    const float* x      = (const float*)d_in[0];
    const float* bias   = (const float*)d_in[1];
    const float* tconst = (const float*)d_in[2];
    const float* sign   = (const float*)d_in[3];
    const float* cnt    = (const float*)d_in[4];
    const float* strg   = (const float*)d_in[5];
    const int*   src    = (const int*)d_in[6];
    const int*   tgt    = (const int*)d_in[7];
    float*       out    = (float*)d_out;

    static const int DYN = ECAP * (int)sizeof(float4);   // 63488 B
    cudaFuncSetAttribute(net_kernel, cudaFuncAttributeMaxDynamicSharedMemorySize, DYN);

    init_kernel<<<128, 512>>>();
    net_kernel<<<NCTA, NTHREADS, DYN>>>(x, bias, tconst, sign, cnt, strg, src, tgt, out);
}

// round 10
// speedup vs baseline: 1.3232x; 1.2000x over previous
#include <cuda_runtime.h>
#include <cuda_fp16.h>

#define N_NODES  50000
#define N_EDGES  1600000
#define BATCH    4
#define T_STEPS  50
#define DT_CONST 0.02f

#define NTHREADS 512
#define TN       (T_STEPS * N_NODES)
#define QPC      (NTHREADS / 4)     // 128 quads per CTA
#define MAXCTA   512                // scan width bound; >= 3*160 SMs
#define MAXQ     (MAXCTA * QPC)
#define ECAP     4096               // smem edge capacity per CTA (16KB packed)

// ---------------- device scratch (static, no allocation) ----------------
__device__ int      g_deg[N_NODES];
__device__ int      g_rowptr[N_NODES + 1];
__device__ int      g_cursor[N_NODES];
__device__ int      g_rowLo[MAXQ + 1];      // quad -> first row of its contiguous range
__device__ unsigned g_wp[N_EDGES];          // packed edge: (src<<16) | fp16(w)
__device__ float2   g_ab[N_NODES];          // {alpha, bias}
__device__ float    g_Vf[N_NODES * 4];      // membrane potential [n][b]
__device__ float4   g_R[2][N_NODES];        // double-buffered relu(v) fp32
__device__ int      g_blockSum[MAXCTA];
__device__ unsigned g_bar;

// ---------------- grid barrier (monotone counter, reset by init kernel) ----------------
__device__ __forceinline__ void grid_bar(unsigned k) {
    __syncthreads();
    if (threadIdx.x == 0) {
        __threadfence();
        atomicAdd(&g_bar, 1u);
        const unsigned target = k * gridDim.x;
        while (*(volatile unsigned*)&g_bar < target) { }
    }
    __syncthreads();
}

// ---------------- block-wide inclusive scan (Kogge-Stone in smem) ----------------
__device__ int block_scan_incl(int v) {
    __shared__ int ss[NTHREADS];
    const int tid = threadIdx.x;
    ss[tid] = v;
    __syncthreads();
#pragma unroll
    for (int off = 1; off < NTHREADS; off <<= 1) {
        int t = 0;
        if (tid >= off) t = ss[tid - off];
        __syncthreads();
        if (tid >= off) ss[tid] += t;
        __syncthreads();
    }
    return ss[tid];
}

__device__ __forceinline__ int quad_of_offset(int off, int nquads) {
    return (int)(((long long)off * nquads) / N_EDGES);
}

// ---------------- init kernel: reset per-launch mutable state ----------------
__global__ void init_kernel() {
    int i = blockIdx.x * blockDim.x + threadIdx.x;
    if (i == 0) g_bar = 0u;
    for (int n = i; n < N_NODES; n += gridDim.x * blockDim.x) g_deg[n] = 0;
}

// ---------------- fallback hot loop (global edges; proven R5 shape) ----------------
__device__ __noinline__ void run_steps_fallback(
    int rowA, int rowB, int q, unsigned qmask,
    const float* __restrict__ x, float* __restrict__ out,
    unsigned& barK)
{
    for (int t = 0; t < T_STEPS; t++) {
        const float4* __restrict__ Rc  = g_R[t & 1];
        float*        __restrict__ Rnf = (float*)(g_R[(t + 1) & 1]);
        const float*  __restrict__ xt  = x + t * N_NODES;
        float*        __restrict__ ot  = out + t * N_NODES;

        for (int r = rowA; r < rowB; ++r) {
            const int beg = g_rowptr[r];
            const int end = g_rowptr[r + 1];
            const float xv = __ldcg(xt + q * TN + r);
            float a0 = 0.f, a1 = 0.f, a2 = 0.f, a3 = 0.f;
            for (int e = beg + q; e < end; e += 4) {
                unsigned u = __ldg(&g_wp[e]);
                float w = __half2float(__ushort_as_half((unsigned short)(u & 0xFFFFu)));
                float4 rv = __ldcg(&Rc[u >> 16]);
                a0 = fmaf(w, rv.x, a0); a1 = fmaf(w, rv.y, a1);
                a2 = fmaf(w, rv.z, a2); a3 = fmaf(w, rv.w, a3);
            }
#pragma unroll
            for (int off = 1; off < 4; off <<= 1) {
                a0 += __shfl_xor_sync(qmask, a0, off);
                a1 += __shfl_xor_sync(qmask, a1, off);
                a2 += __shfl_xor_sync(qmask, a2, off);
                a3 += __shfl_xor_sync(qmask, a3, off);
            }
            float acc = (q == 0) ? a0 : (q == 1) ? a1 : (q == 2) ? a2 : a3;
            float2 ab = g_ab[r];
            float  v  = g_Vf[4 * r + q];
            v = fmaf(ab.x, (ab.y - v) + (acc + xv), v);
            g_Vf[4 * r + q] = v;
            float rr = fmaxf(v, 0.0f);
            Rnf[4 * r + q] = rr;
            ot[q * TN + r] = rr;
        }
        if (t != T_STEPS - 1) grid_bar(++barK);
    }
}

// ---------------- main persistent kernel ----------------
__global__ void __launch_bounds__(NTHREADS, 3) net_kernel(
    const float* __restrict__ x,       // [B, T, N]
    const float* __restrict__ bias,    // [N]
    const float* __restrict__ tconst,  // [N]
    const float* __restrict__ sign,    // [E]
    const float* __restrict__ cnt,     // [E]
    const float* __restrict__ strg,    // [E]
    const int*   __restrict__ src,     // [E]
    const int*   __restrict__ tgt,     // [E]
    float*       __restrict__ out,     // [B, T, N]
    int chunk)
{
    __shared__ unsigned s_ws[ECAP];    // packed edge slice (16KB)

    const int tid   = threadIdx.x;
    const int bid   = blockIdx.x;
    const int ncta  = gridDim.x;
    const int gtid  = bid * NTHREADS + tid;
    const int nthr  = ncta * NTHREADS;
    const int nquads = ncta * QPC;
    unsigned barK = 0;

    // ---- Pass A: degree histogram over targets ----
    for (int e = gtid; e < N_EDGES; e += nthr)
        atomicAdd(&g_deg[tgt[e]], 1);
    grid_bar(++barK);

    // ---- Pass B1: per-CTA chunk sums ----
    {
        const int n = bid * chunk + tid;
        int v = (tid < chunk && n < N_NODES) ? g_deg[n] : 0;
        int incl = block_scan_incl(v);
        if (tid == NTHREADS - 1) g_blockSum[bid] = incl;
    }
    grid_bar(++barK);

    // ---- Pass B2: CTA0 exclusive-scans the block sums ----
    if (bid == 0) {
        int v = (tid < ncta) ? g_blockSum[tid] : 0;
        int incl = block_scan_incl(v);
        if (tid < ncta) g_blockSum[tid] = incl - v;
    }
    grid_bar(++barK);

    // ---- Pass B3: per-chunk exclusive scan -> row_ptr & cursor ----
    {
        const int n = bid * chunk + tid;
        int v = (tid < chunk && n < N_NODES) ? g_deg[n] : 0;
        int incl = block_scan_incl(v);
        if (tid < chunk && n < N_NODES) {
            int rp = g_blockSum[bid] + incl - v;
            g_rowptr[n] = rp;
            g_cursor[n] = rp;
        }
        if (gtid == 0) g_rowptr[N_NODES] = N_EDGES;
    }
    grid_bar(++barK);

    // ---- Pass C: scatter packed edges into CSR slots ----
    for (int e = gtid; e < N_EDGES; e += nthr) {
        float w = sign[e] * fmaxf(cnt[e], 0.0f) * fmaxf(strg[e], 0.0f);
        int  t = tgt[e];
        int  p = atomicAdd(&g_cursor[t], 1);
        unsigned hw = (unsigned)__half_as_ushort(__float2half_rn(w));
        g_wp[p] = ((unsigned)src[e] << 16) | hw;
    }

    // ---- Edge-balanced quad->row-range partition ----
    for (int r = gtid; r <= N_NODES; r += nthr) {
        int a, b;
        if (r == N_NODES) {
            a = min(quad_of_offset(g_rowptr[N_NODES - 1], nquads), nquads - 1) + 1;
            b = nquads;
        } else {
            b = min(quad_of_offset(g_rowptr[r], nquads), nquads - 1);
            a = (r == 0) ? 0 : min(quad_of_offset(g_rowptr[r - 1], nquads), nquads - 1) + 1;
        }
        for (int qq = a; qq <= b; qq++) g_rowLo[qq] = r;
    }

    // ---- Pass D: node state init ----
    for (int n = gtid; n < N_NODES; n += nthr) {
        float b   = bias[n];
        float tau = fmaxf(tconst[n], DT_CONST);
        g_ab[n] = make_float2(DT_CONST / tau, b);
        float r = fmaxf(b, 0.0f);
        g_Vf[4 * n + 0] = b; g_Vf[4 * n + 1] = b;
        g_Vf[4 * n + 2] = b; g_Vf[4 * n + 3] = b;
        g_R[0][n] = make_float4(r, r, r, r);
    }
    grid_bar(++barK);   // edges + partition + state all visible now

    // ---- Stage this CTA's packed edge slice into shared memory ----
    const int rowA_cta = g_rowLo[bid * QPC];
    const int rowB_cta = g_rowLo[(bid + 1) * QPC];
    const int ebase    = g_rowptr[rowA_cta];
    const int ecnt     = g_rowptr[rowB_cta] - ebase;
    const bool fits    = (ecnt <= ECAP);
    if (fits) {
        for (int i = tid; i < ecnt; i += NTHREADS)
            s_ws[i] = g_wp[ebase + i];
    }
    __syncthreads();

    const int q    = tid & 3;
    const int qid  = gtid >> 2;
    const int rowA = g_rowLo[qid];
    const int rowB = g_rowLo[qid + 1];
    const unsigned qmask = 0xFu << (tid & 28);

    if (!fits) {
        run_steps_fallback(rowA, rowB, q, qmask, x, out, barK);
        return;
    }

    // ---- Hot loop: 50 steps, quad-per-row-range gather SpMV + Euler update ----
    for (int t = 0; t < T_STEPS; t++) {
        const float4* __restrict__ Rc  = g_R[t & 1];
        float*        __restrict__ Rnf = (float*)(g_R[(t + 1) & 1]);
        const float*  __restrict__ xt  = x + t * N_NODES;
        float*        __restrict__ ot  = out + t * N_NODES;

        for (int r = rowA; r < rowB; ++r) {
            const int beg = g_rowptr[r];          // L1-hit (same addr each step)
            const int end = g_rowptr[r + 1];
            const float xv = __ldcg(xt + q * TN + r);

            unsigned long long a01 = 0ull, a23 = 0ull;   // f32x2 accumulators
#pragma unroll 4
            for (int e = beg + q; e < end; e += 4) {
                unsigned u = s_ws[e - ebase];     // LDS.32 (1 wavefront)
                float w = __half2float(__ushort_as_half((unsigned short)(u & 0xFFFFu)));
                unsigned long long w2, r01, r23;
                asm("mov.b64 %0, {%1, %1};" : "=l"(w2) : "f"(w));
                asm volatile("ld.global.cg.v2.b64 {%0, %1}, [%2];"
                             : "=l"(r01), "=l"(r23) : "l"(Rc + (u >> 16)));
                asm("fma.rn.f32x2 %0, %1, %2, %3;" : "=l"(a01) : "l"(w2), "l"(r01), "l"(a01));
                asm("fma.rn.f32x2 %0, %1, %2, %3;" : "=l"(a23) : "l"(w2), "l"(r23), "l"(a23));
            }
            // quad reduction with quad-local mask (quads diverge; quad lanes don't)
#pragma unroll
            for (int off = 1; off < 4; off <<= 1) {
                unsigned long long b01 = __shfl_xor_sync(qmask, a01, off);
                unsigned long long b23 = __shfl_xor_sync(qmask, a23, off);
                asm("add.rn.f32x2 %0, %1, %2;" : "=l"(a01) : "l"(a01), "l"(b01));
                asm("add.rn.f32x2 %0, %1, %2;" : "=l"(a23) : "l"(a23), "l"(b23));
            }
            unsigned long long sel = (q < 2) ? a01 : a23;
            float lo, hi;
            asm("mov.b64 {%0, %1}, %2;" : "=f"(lo), "=f"(hi) : "l"(sel));
            float acc = (q & 1) ? hi : lo;

            float2 ab = g_ab[r];                  // L1-hit
            float  v  = g_Vf[4 * r + q];          // L1-hit
            v = fmaf(ab.x, (ab.y - v) + (acc + xv), v);
            g_Vf[4 * r + q] = v;
            float rr = fmaxf(v, 0.0f);
            Rnf[4 * r + q] = rr;
            ot[q * TN + r] = rr;
        }
        if (t != T_STEPS - 1) grid_bar(++barK);
    }
}

extern "C" void kernel_launch(void* const* d_in, const int* in_sizes, int n_in,
                              void* d_out, int out_size) {
    const float* x      = (const float*)d_in[0];
    const float* bias   = (const float*)d_in[1];
    const float* tconst = (const float*)d_in[2];
    const float* sign   = (const float*)d_in[3];
    const float* cnt    = (const float*)d_in[4];
    const float* strg   = (const float*)d_in[5];
    const int*   src    = (const int*)d_in[6];
    const int*   tgt    = (const int*)d_in[7];
    float*       out    = (float*)d_out;

    // Attribute query only (no alloc, no sync) -- capture-safe, deterministic.
    int nsm = 148;
    cudaDeviceGetAttribute(&nsm, cudaDevAttrMultiProcessorCount, 0);
    int ncta = nsm * 3;
    if (ncta > MAXCTA) ncta = MAXCTA;
    int chunk = (N_NODES + ncta - 1) / ncta;

    init_kernel<<<128, 512>>>();
    net_kernel<<<ncta, NTHREADS>>>(x, bias, tconst, sign, cnt, strg, src, tgt, out, chunk);
}